// round 11
// baseline (speedup 1.0000x reference)
#include <cuda_runtime.h>
#include <cuda_fp16.h>
#include <cstdint>
#include <cstddef>

// Problem constants
#define BB   32
#define HH   32
#define WW   32
#define CC   256
#define SS   (HH * WW)        // 1024
#define GG   32
#define CPG  (CC / GG)        // 8
#define MS   (BB * SS)        // 32768
#define EPS  1e-5f
#define ESHIFT 6.0f

// GEMM tile config: CTA 64x128, 8 warps (4m x 2n), warp tile 16x64,
// BK=32, 3 stages, 3 CTAs/SM.
#define TM 64
#define TN 128
#define BK 32
#define NSTAGE 3
#define RS 40                              // padded row stride in halves (80 B)
#define RSB2 272                           // TRANSB row stride in BYTES
#define A_BYTES (TM * RS * 2)              // 5120
#define B_BYTES (TN * RS * 2)              // 10240
#define STAGE_BYTES (A_BYTES + B_BYTES)    // 15360
#define SMEM_BYTES (NSTAGE * STAGE_BYTES)  // 46080

// ---------------------------------------------------------------------------
// Scratch
// ---------------------------------------------------------------------------
__device__ __half g_ft  [(size_t)MS * CC];
__device__ __half g_qkv [(size_t)MS * 3 * CC];
__device__ __half g_p   [(size_t)BB * SS * SS];
__device__ float  g_rsum[(size_t)MS];
__device__ __half g_at  [(size_t)MS * CC];
__device__ __half g_wt  [4 * CC * CC];
__device__ float  g_bqkv[3 * CC];

// ---------------------------------------------------------------------------
// Helpers
// ---------------------------------------------------------------------------
__device__ __forceinline__ uint32_t smem_u32(const void* p) {
    uint32_t a;
    asm("{ .reg .u64 t; cvta.to.shared.u64 t, %1; cvt.u32.u64 %0, t; }" : "=r"(a) : "l"(p));
    return a;
}
__device__ __forceinline__ void cp16(uint32_t s, const void* g) {
    asm volatile("cp.async.cg.shared.global [%0], [%1], 16;" :: "r"(s), "l"(g));
}
__device__ __forceinline__ void ldmx4(uint32_t* r, uint32_t addr) {
    asm volatile("ldmatrix.sync.aligned.m8n8.x4.shared.b16 {%0,%1,%2,%3}, [%4];"
        : "=r"(r[0]), "=r"(r[1]), "=r"(r[2]), "=r"(r[3]) : "r"(addr));
}
__device__ __forceinline__ void ldmx4t(uint32_t* r, uint32_t addr) {
    asm volatile("ldmatrix.sync.aligned.m8n8.x4.trans.shared.b16 {%0,%1,%2,%3}, [%4];"
        : "=r"(r[0]), "=r"(r[1]), "=r"(r[2]), "=r"(r[3]) : "r"(addr));
}
__device__ __forceinline__ void mma_f16(float* d,
                                        uint32_t a0, uint32_t a1, uint32_t a2, uint32_t a3,
                                        uint32_t b0, uint32_t b1) {
    asm volatile(
        "mma.sync.aligned.m16n8k16.row.col.f32.f16.f16.f32 "
        "{%0,%1,%2,%3}, {%4,%5,%6,%7}, {%8,%9}, {%0,%1,%2,%3};"
        : "+f"(d[0]), "+f"(d[1]), "+f"(d[2]), "+f"(d[3])
        : "r"(a0), "r"(a1), "r"(a2), "r"(a3), "r"(b0), "r"(b1));
}

// ---------------------------------------------------------------------------
// GroupNorm -> fp16 (single global read: x cached in registers)
// Blocks 0..31 also zero g_rsum.
// ---------------------------------------------------------------------------
__global__ void gn_kernel(const float* __restrict__ x,
                          const float* __restrict__ scale,
                          const float* __restrict__ bias)
{
    const int b = blockIdx.x / GG, g = blockIdx.x % GG, tid = threadIdx.x;

    if (blockIdx.x < 32) {
        float4* rz = (float4*)(g_rsum + (size_t)blockIdx.x * 1024);
        rz[tid] = make_float4(0.f, 0.f, 0.f, 0.f);
    }

    const float* xb = x + (size_t)b * SS * CC + g * CPG;

    float4 xv[4][2];
    float sum = 0.f, ssq = 0.f;
#pragma unroll
    for (int kk = 0; kk < 4; kk++) {
        const int s = tid + kk * 256;
        const float4* p = (const float4*)(xb + (size_t)s * CC);
        xv[kk][0] = p[0];
        xv[kk][1] = p[1];
        const float4 a = xv[kk][0], c = xv[kk][1];
        sum += a.x + a.y + a.z + a.w + c.x + c.y + c.z + c.w;
        ssq += a.x*a.x + a.y*a.y + a.z*a.z + a.w*a.w
             + c.x*c.x + c.y*c.y + c.z*c.z + c.w*c.w;
    }
    __shared__ float r0[256], r1[256];
    r0[tid] = sum; r1[tid] = ssq;
    __syncthreads();
    for (int off = 128; off > 0; off >>= 1) {
        if (tid < off) { r0[tid] += r0[tid + off]; r1[tid] += r1[tid + off]; }
        __syncthreads();
    }
    const float mean = r0[0] * (1.f / 8192.f);
    const float var  = r1[0] * (1.f / 8192.f) - mean * mean;
    const float inv  = rsqrtf(var + EPS);

    float sc[CPG], bi[CPG];
#pragma unroll
    for (int c = 0; c < CPG; c++) {
        sc[c] = scale[g * CPG + c] * inv;
        bi[c] = bias [g * CPG + c];
    }
    __half* fb = g_ft + (size_t)b * SS * CC + g * CPG;
#pragma unroll
    for (int kk = 0; kk < 4; kk++) {
        const int s = tid + kk * 256;
        __half2* fo = (__half2*)(fb + (size_t)s * CC);
        const float* xi = (const float*)&xv[kk][0];
#pragma unroll
        for (int c = 0; c < 4; c++) {
            const float v0 = (xi[2*c]   - mean) * sc[2*c]   + bi[2*c];
            const float v1 = (xi[2*c+1] - mean) * sc[2*c+1] + bi[2*c+1];
            fo[c] = __floats2half2_rn(v0, v1);
        }
    }
}

// ---------------------------------------------------------------------------
// Weight transpose -> fp16; block (0,0,0) also packs the QKV biases.
// ---------------------------------------------------------------------------
__global__ void transpose_w(const float* __restrict__ Wq, const float* __restrict__ Wk,
                            const float* __restrict__ Wv, const float* __restrict__ Wo,
                            const float* __restrict__ bq, const float* __restrict__ bk,
                            const float* __restrict__ bv)
{
    __shared__ float t[32][33];
    const int i = blockIdx.z;
    const float* W = (i == 0) ? Wq : (i == 1) ? Wk : (i == 2) ? Wv : Wo;
    const int kb = blockIdx.x * 32, nb = blockIdx.y * 32;
    const int tx = threadIdx.x, ty = threadIdx.y;
    const int tid = ty * 32 + tx;

    if (i == 0 && blockIdx.x == 0 && blockIdx.y == 0) {
        g_bqkv[tid]          = bq[tid];
        g_bqkv[tid + CC]     = bk[tid];
        g_bqkv[tid + 2 * CC] = bv[tid];
    }

#pragma unroll
    for (int j = 0; j < 4; j++)
        t[ty + j * 8][tx] = W[(size_t)(kb + ty + j * 8) * CC + nb + tx];
    __syncthreads();
    __half* out = g_wt + (size_t)i * CC * CC;
#pragma unroll
    for (int j = 0; j < 4; j++)
        out[(size_t)(nb + ty + j * 8) * CC + kb + tx] = __float2half_rn(t[tx][ty + j * 8]);
}

// ---------------------------------------------------------------------------
// fp16 tensor-core GEMM. CTA 64x128, warp tile 16x64 (8 warps, 4m x 2n),
// BK=32, 3-stage ring, ldmatrix.x4, 3 CTAs/SM.
// C[m,n] = alpha * sum_k A[m,k]*B[n,k] (+bias)(+resid)
// TRANSB: B stored [K,N] row-major; loaded via ldmatrix.trans.
// do_exp: out = exp(val - ESHIFT), rowsum accumulated into rsum_out.
// rowinv: out *= 1/rowinv[batch*SS + r].
// ---------------------------------------------------------------------------
template <int TRANSB>
__global__ void __launch_bounds__(256, 3)
mma_gemm(const __half* __restrict__ A, const __half* __restrict__ B,
         const float* __restrict__ bias, const float* __restrict__ resid,
         const float* __restrict__ rowinv, float* __restrict__ rsum_out,
         void* __restrict__ Cvoid,
         int K, int lda, int ldb, int ldc,
         float alpha, int out_half, int do_exp, int swapxy,
         long long sA, long long sB, long long sC)
{
    extern __shared__ __half sm[];
    const int batch = blockIdx.z;
    A += (size_t)batch * sA;
    B += (size_t)batch * sB;
    if (rowinv)   rowinv   += (size_t)batch * SS;
    if (rsum_out) rsum_out += (size_t)batch * SS;

    const int tid  = threadIdx.x;
    const int lane = tid & 31;
    const int wid  = tid >> 5;
    const int warp_m = wid & 3;           // 4 warps over M (16 rows each)
    const int warp_n = wid >> 2;          // 2 warps over N (64 cols each)
    const int bx = swapxy ? blockIdx.y : blockIdx.x;
    const int by = swapxy ? blockIdx.x : blockIdx.y;
    const int row0 = bx * TM;
    const int col0 = by * TN;

    const __half* Ab = A + (size_t)row0 * lda;
    const __half* Bb = TRANSB ? (B + col0) : (B + (size_t)col0 * ldb);
    const uint32_t sbase = smem_u32(sm);

    auto load_stage = [&](int k0, int st) {
        const uint32_t abase = sbase + st * STAGE_BYTES;
        const uint32_t bbase = abase + A_BYTES;
        {   // A: 64 rows x 64 B = 256 chunks, 1 per thread
            const int r  = tid >> 2;
            const int ch = (tid & 3) * 8;        // halves
            cp16(abase + r * (RS * 2) + ch * 2, Ab + (size_t)r * lda + k0 + ch);
        }
        if (TRANSB) {
            // B: 32 key-rows x 256 B = 512 chunks, 2 per thread
#pragma unroll
            for (int i = 0; i < 2; i++) {
                const int id = tid + i * 256;
                const int r  = id >> 4;          // key row 0..31
                const int ch = (id & 15) * 8;
                cp16(bbase + r * RSB2 + ch * 2, Bb + (size_t)(k0 + r) * ldb + ch);
            }
        } else {
            // B: 128 rows x 64 B = 512 chunks, 2 per thread
#pragma unroll
            for (int i = 0; i < 2; i++) {
                const int id = tid + i * 256;
                const int r  = id >> 2;
                const int ch = (id & 3) * 8;
                cp16(bbase + r * (RS * 2) + ch * 2, Bb + (size_t)r * ldb + k0 + ch);
            }
        }
        asm volatile("cp.async.commit_group;" ::: "memory");
    };

    const int quad = lane >> 3;
    const int r8   = lane & 7;
    uint32_t a_off, b_off[4];
    {
        const int row = warp_m * 16 + (lane & 15);
        a_off = (row * RS + (lane >> 4) * 8) * 2;
    }
    if (TRANSB) {
#pragma unroll
        for (int ntp = 0; ntp < 4; ntp++) {
            const int kk = (quad & 1) * 8 + r8;
            const int nn = warp_n * 64 + ntp * 16 + (quad >> 1) * 8;
            b_off[ntp] = A_BYTES + kk * RSB2 + nn * 2;
        }
    } else {
#pragma unroll
        for (int ntp = 0; ntp < 4; ntp++) {
            const int n = warp_n * 64 + ntp * 16 + (quad >> 1) * 8 + r8;
            b_off[ntp] = A_BYTES + (n * RS + (quad & 1) * 8) * 2;
        }
    }
    const uint32_t koffB = TRANSB ? (16 * RSB2) : 32;

    float acc[8][4];
#pragma unroll
    for (int b = 0; b < 8; b++)
#pragma unroll
        for (int c = 0; c < 4; c++) acc[b][c] = 0.f;

    const int nk = K / BK;
    load_stage(0, 0);
    load_stage(BK, 1);

    int st = 0;
    for (int t = 0; t < nk; t++) {
        if (t + 1 < nk) asm volatile("cp.async.wait_group 1;" ::: "memory");
        else            asm volatile("cp.async.wait_group 0;" ::: "memory");
        __syncthreads();

        if (t + 2 < nk) {
            int st2 = st + 2; if (st2 >= NSTAGE) st2 -= NSTAGE;
            load_stage((t + 2) * BK, st2);
        }

        const uint32_t stbase = sbase + st * STAGE_BYTES;

#pragma unroll
        for (int ks = 0; ks < 2; ks++) {          // 2 x k16 = BK
            uint32_t a[4];
            ldmx4(a, stbase + a_off + ks * 32);
            uint32_t b[8][2];
#pragma unroll
            for (int ntp = 0; ntp < 4; ntp++) {
                uint32_t tr[4];
                if (TRANSB) ldmx4t(tr, stbase + b_off[ntp] + ks * koffB);
                else        ldmx4 (tr, stbase + b_off[ntp] + ks * koffB);
                b[2*ntp][0]   = tr[0]; b[2*ntp][1]   = tr[1];
                b[2*ntp+1][0] = tr[2]; b[2*ntp+1][1] = tr[3];
            }
#pragma unroll
            for (int nt = 0; nt < 8; nt++)
                mma_f16(acc[nt], a[0], a[1], a[2], a[3], b[nt][0], b[nt][1]);
        }
        st++; if (st >= NSTAGE) st -= NSTAGE;
    }

    // Epilogue
    const int g  = lane >> 2;
    const int tg = lane & 3;
    if (out_half) {
        __half* C = (__half*)Cvoid + (size_t)batch * sC;
#pragma unroll
        for (int hf = 0; hf < 2; hf++) {
            const int r = row0 + warp_m * 16 + hf * 8 + g;
            __half* Crow = C + (size_t)r * ldc;
            const float rs = rowinv ? (1.f / rowinv[r]) : 1.f;
            float rowpart = 0.f;
#pragma unroll
            for (int nt = 0; nt < 8; nt++) {
                const int cix = col0 + warp_n * 64 + nt * 8 + tg * 2;
                float v0 = acc[nt][hf * 2 + 0] * alpha;
                float v1 = acc[nt][hf * 2 + 1] * alpha;
                if (bias) { v0 += bias[cix]; v1 += bias[cix + 1]; }
                if (do_exp) {
                    v0 = __expf(v0 - ESHIFT); v1 = __expf(v1 - ESHIFT);
                    rowpart += v0 + v1;
                }
                v0 *= rs; v1 *= rs;
                *(__half2*)&Crow[cix] = __floats2half2_rn(v0, v1);
            }
            if (do_exp) {
                rowpart += __shfl_xor_sync(0xFFFFFFFF, rowpart, 1);
                rowpart += __shfl_xor_sync(0xFFFFFFFF, rowpart, 2);
                if (tg == 0 && rsum_out) atomicAdd(&rsum_out[r], rowpart);
            }
        }
    } else {
        float* C = (float*)Cvoid + (size_t)batch * sC;
        const float* R = resid ? resid + (size_t)batch * sC : nullptr;
#pragma unroll
        for (int hf = 0; hf < 2; hf++) {
            const int r = row0 + warp_m * 16 + hf * 8 + g;
            float* Crow = C + (size_t)r * ldc;
            const float* Rrow = R ? R + (size_t)r * ldc : nullptr;
#pragma unroll
            for (int nt = 0; nt < 8; nt++) {
                const int cix = col0 + warp_n * 64 + nt * 8 + tg * 2;
                float v0 = acc[nt][hf * 2 + 0] * alpha;
                float v1 = acc[nt][hf * 2 + 1] * alpha;
                if (bias) { v0 += bias[cix]; v1 += bias[cix + 1]; }
                if (Rrow) { v0 += Rrow[cix]; v1 += Rrow[cix + 1]; }
                *(float2*)&Crow[cix] = make_float2(v0, v1);
            }
        }
    }
}

// ---------------------------------------------------------------------------
// Launch
// ---------------------------------------------------------------------------
extern "C" void kernel_launch(void* const* d_in, const int* in_sizes, int n_in,
                              void* d_out, int out_size)
{
    const float* x   = (const float*)d_in[0];
    const float* gsc = (const float*)d_in[1];
    const float* gbi = (const float*)d_in[2];
    const float* Wq  = (const float*)d_in[3];
    const float* bq  = (const float*)d_in[4];
    const float* Wk  = (const float*)d_in[5];
    const float* bk  = (const float*)d_in[6];
    const float* Wv  = (const float*)d_in[7];
    const float* bv  = (const float*)d_in[8];
    const float* Wo  = (const float*)d_in[9];
    const float* bo  = (const float*)d_in[10];
    float* out = (float*)d_out;

    cudaFuncSetAttribute(mma_gemm<0>, cudaFuncAttributeMaxDynamicSharedMemorySize,
                         SMEM_BYTES);
    cudaFuncSetAttribute(mma_gemm<1>, cudaFuncAttributeMaxDynamicSharedMemorySize,
                         SMEM_BYTES);

    __half *ft, *qkv, *pb, *at, *wt;
    float *bqkv, *rsum;
    cudaGetSymbolAddress((void**)&ft,   g_ft);
    cudaGetSymbolAddress((void**)&qkv,  g_qkv);
    cudaGetSymbolAddress((void**)&pb,   g_p);
    cudaGetSymbolAddress((void**)&at,   g_at);
    cudaGetSymbolAddress((void**)&wt,   g_wt);
    cudaGetSymbolAddress((void**)&bqkv, g_bqkv);
    cudaGetSymbolAddress((void**)&rsum, g_rsum);

    const long long sQKV = (long long)SS * 3 * CC;
    const long long sBSS = (long long)SS * SS;
    const long long sBSC = (long long)SS * CC;

    // 1) GroupNorm (+rsum zero), weight transpose (+bias pack)
    gn_kernel<<<BB * GG, 256>>>(x, gsc, gbi);
    transpose_w<<<dim3(8, 8, 4), dim3(32, 8)>>>(Wq, Wk, Wv, Wo, bq, bk, bv);

    // 2) fused QKV projection -> half
    mma_gemm<0><<<dim3((3 * CC) / TN, MS / TM, 1), 256, SMEM_BYTES>>>(
        ft, wt, bqkv, nullptr, nullptr, nullptr, qkv,
        CC, CC, CC, 3 * CC, 1.f, 1, 0, 1, 0, 0, 0);

    // 3) u = exp(QK^T/16 - ESHIFT) per batch -> half; row sums accumulated
    mma_gemm<0><<<dim3(SS / TM, SS / TN, BB), 256, SMEM_BYTES>>>(
        qkv + 0, qkv + CC, nullptr, nullptr, nullptr, rsum, pb,
        CC, 3 * CC, 3 * CC, SS, 0.0625f, 1, 1, 0, sQKV, sQKV, sBSS);

    // 4) attn = (u V) / S per batch -> half; V read in [key][d] layout (TRANSB)
    mma_gemm<1><<<dim3(SS / TM, CC / TN, BB), 256, SMEM_BYTES>>>(
        pb, qkv + 2 * CC, nullptr, nullptr, rsum, nullptr, at,
        SS, SS, 3 * CC, CC, 1.f, 1, 0, 0, sBSS, sQKV, sBSC);

    // 5) out = attn Wo + bo + x -> f32
    mma_gemm<0><<<dim3(CC / TN, MS / TM, 1), 256, SMEM_BYTES>>>(
        at, wt + 3 * CC * CC, bo, x, nullptr, nullptr, out,
        CC, CC, CC, CC, 1.f, 0, 0, 1, 0, 0, 0);
}

// round 12
// speedup vs baseline: 1.1967x; 1.1967x over previous
#include <cuda_runtime.h>
#include <cuda_fp16.h>
#include <cstdint>
#include <cstddef>

// Problem constants
#define BB   32
#define HH   32
#define WW   32
#define CC   256
#define SS   (HH * WW)        // 1024
#define GG   32
#define CPG  (CC / GG)        // 8
#define MS   (BB * SS)        // 32768
#define EPS  1e-5f
#define ESHIFT 6.0f           // exp shift: u = exp(logit - ESHIFT)

// GEMM tile config (fp16 operands, fp32 accum) — R10 proven geometry
#define BM 128
#define BN 128
#define BK 64
#define NSTAGE 3
#define RS 72                             // padded row stride in halves (144 B)
#define RSB2 272                          // TRANSB row stride in BYTES (136 halves)
#define A_SZH (BM * RS)
#define B_SZH (BN * RS)
#define STAGE_H (A_SZH + B_SZH)
#define SMEM_BYTES (NSTAGE * STAGE_H * 2) // 110592 bytes

// ---------------------------------------------------------------------------
// Scratch
// ---------------------------------------------------------------------------
__device__ __half g_ft  [(size_t)MS * CC];
__device__ __half g_qkv [(size_t)MS * 3 * CC];
__device__ __half g_p   [(size_t)BB * SS * SS];   // unnormalized exp(logits)
__device__ float  g_rsum[(size_t)MS];             // rowsum per (batch,query)
__device__ __half g_at  [(size_t)MS * CC];
__device__ __half g_wt  [4 * CC * CC];
__device__ float  g_bqkv[3 * CC];

// ---------------------------------------------------------------------------
// Helpers
// ---------------------------------------------------------------------------
__device__ __forceinline__ uint32_t smem_u32(const void* p) {
    uint32_t a;
    asm("{ .reg .u64 t; cvta.to.shared.u64 t, %1; cvt.u32.u64 %0, t; }" : "=r"(a) : "l"(p));
    return a;
}
__device__ __forceinline__ void cp16(uint32_t s, const void* g) {
    asm volatile("cp.async.cg.shared.global [%0], [%1], 16;" :: "r"(s), "l"(g));
}
__device__ __forceinline__ void ldmx4(uint32_t* r, uint32_t addr) {
    asm volatile("ldmatrix.sync.aligned.m8n8.x4.shared.b16 {%0,%1,%2,%3}, [%4];"
        : "=r"(r[0]), "=r"(r[1]), "=r"(r[2]), "=r"(r[3]) : "r"(addr));
}
__device__ __forceinline__ void ldmx4t(uint32_t* r, uint32_t addr) {
    asm volatile("ldmatrix.sync.aligned.m8n8.x4.trans.shared.b16 {%0,%1,%2,%3}, [%4];"
        : "=r"(r[0]), "=r"(r[1]), "=r"(r[2]), "=r"(r[3]) : "r"(addr));
}
__device__ __forceinline__ void mma_f16(float* d,
                                        uint32_t a0, uint32_t a1, uint32_t a2, uint32_t a3,
                                        uint32_t b0, uint32_t b1) {
    asm volatile(
        "mma.sync.aligned.m16n8k16.row.col.f32.f16.f16.f32 "
        "{%0,%1,%2,%3}, {%4,%5,%6,%7}, {%8,%9}, {%0,%1,%2,%3};"
        : "+f"(d[0]), "+f"(d[1]), "+f"(d[2]), "+f"(d[3])
        : "r"(a0), "r"(a1), "r"(a2), "r"(a3), "r"(b0), "r"(b1));
}

// ---------------------------------------------------------------------------
// GroupNorm -> fp16; blocks 0..31 also zero g_rsum (saves a launch)
// ---------------------------------------------------------------------------
__global__ void gn_kernel(const float* __restrict__ x,
                          const float* __restrict__ scale,
                          const float* __restrict__ bias)
{
    const int b = blockIdx.x / GG, g = blockIdx.x % GG, tid = threadIdx.x;

    if (blockIdx.x < 32) {
        float4* rz = (float4*)(g_rsum + (size_t)blockIdx.x * 1024);
        rz[tid] = make_float4(0.f, 0.f, 0.f, 0.f);
    }

    const float* xb = x + (size_t)b * SS * CC + g * CPG;

    float4 xv[4][2];
    float sum = 0.f, ssq = 0.f;
#pragma unroll
    for (int kk = 0; kk < 4; kk++) {
        const int s = tid + kk * 256;
        const float4* p = (const float4*)(xb + (size_t)s * CC);
        xv[kk][0] = p[0];
        xv[kk][1] = p[1];
        const float4 a = xv[kk][0], c = xv[kk][1];
        sum += a.x + a.y + a.z + a.w + c.x + c.y + c.z + c.w;
        ssq += a.x*a.x + a.y*a.y + a.z*a.z + a.w*a.w
             + c.x*c.x + c.y*c.y + c.z*c.z + c.w*c.w;
    }
    __shared__ float r0[256], r1[256];
    r0[tid] = sum; r1[tid] = ssq;
    __syncthreads();
    for (int off = 128; off > 0; off >>= 1) {
        if (tid < off) { r0[tid] += r0[tid + off]; r1[tid] += r1[tid + off]; }
        __syncthreads();
    }
    const float mean = r0[0] * (1.f / 8192.f);
    const float var  = r1[0] * (1.f / 8192.f) - mean * mean;
    const float inv  = rsqrtf(var + EPS);

    float sc[CPG], bi[CPG];
#pragma unroll
    for (int c = 0; c < CPG; c++) {
        sc[c] = scale[g * CPG + c] * inv;
        bi[c] = bias [g * CPG + c];
    }
    __half* fb = g_ft + (size_t)b * SS * CC + g * CPG;
#pragma unroll
    for (int kk = 0; kk < 4; kk++) {
        const int s = tid + kk * 256;
        __half2* fo = (__half2*)(fb + (size_t)s * CC);
        const float* xi = (const float*)&xv[kk][0];
#pragma unroll
        for (int c = 0; c < 4; c++) {
            const float v0 = (xi[2*c]   - mean) * sc[2*c]   + bi[2*c];
            const float v1 = (xi[2*c+1] - mean) * sc[2*c+1] + bi[2*c+1];
            fo[c] = __floats2half2_rn(v0, v1);
        }
    }
}

// ---------------------------------------------------------------------------
// Weight transpose -> fp16; block (0,0,0) also packs the QKV biases.
// ---------------------------------------------------------------------------
__global__ void transpose_w(const float* __restrict__ Wq, const float* __restrict__ Wk,
                            const float* __restrict__ Wv, const float* __restrict__ Wo,
                            const float* __restrict__ bq, const float* __restrict__ bk,
                            const float* __restrict__ bv)
{
    __shared__ float t[32][33];
    const int i = blockIdx.z;
    const float* W = (i == 0) ? Wq : (i == 1) ? Wk : (i == 2) ? Wv : Wo;
    const int kb = blockIdx.x * 32, nb = blockIdx.y * 32;
    const int tx = threadIdx.x, ty = threadIdx.y;
    const int tid = ty * 32 + tx;

    if (i == 0 && blockIdx.x == 0 && blockIdx.y == 0) {
        g_bqkv[tid]          = bq[tid];
        g_bqkv[tid + CC]     = bk[tid];
        g_bqkv[tid + 2 * CC] = bv[tid];
    }

#pragma unroll
    for (int j = 0; j < 4; j++)
        t[ty + j * 8][tx] = W[(size_t)(kb + ty + j * 8) * CC + nb + tx];
    __syncthreads();
    __half* out = g_wt + (size_t)i * CC * CC;
#pragma unroll
    for (int j = 0; j < 4; j++)
        out[(size_t)(nb + ty + j * 8) * CC + kb + tx] = __float2half_rn(t[tx][ty + j * 8]);
}

// ---------------------------------------------------------------------------
// fp16 tensor-core GEMM. CTA 128x128, warp 32x64, BK=64, 3-stage ring,
// ldmatrix.x4, 2 CTAs/SM.  (R10 proven configuration.)
// C[m,n] = alpha * sum_k A[m,k]*B[n,k] (+bias)(+resid)
// TRANSB: B stored [K,N] row-major (ldb = row stride); loaded via ldmatrix.trans.
// do_exp: out = exp(val - ESHIFT) (half) and accumulate row sums into rsum_out.
// rowinv: out *= 1/rowinv[batch*SS + r].
// ---------------------------------------------------------------------------
template <int TRANSB>
__global__ void __launch_bounds__(256, 2)
mma_gemm(const __half* __restrict__ A, const __half* __restrict__ B,
         const float* __restrict__ bias, const float* __restrict__ resid,
         const float* __restrict__ rowinv, float* __restrict__ rsum_out,
         void* __restrict__ Cvoid,
         int K, int lda, int ldb, int ldc,
         float alpha, int out_half, int do_exp, int swapxy,
         long long sA, long long sB, long long sC)
{
    extern __shared__ __half sm[];
    const int batch = blockIdx.z;
    A += (size_t)batch * sA;
    B += (size_t)batch * sB;
    if (rowinv)   rowinv   += (size_t)batch * SS;
    if (rsum_out) rsum_out += (size_t)batch * SS;

    const int tid  = threadIdx.x;
    const int lane = tid & 31;
    const int wid  = tid >> 5;
    const int warp_m = wid & 3;
    const int warp_n = wid >> 2;
    const int bx = swapxy ? blockIdx.y : blockIdx.x;
    const int by = swapxy ? blockIdx.x : blockIdx.y;
    const int row0 = bx * BM;
    const int col0 = by * BN;

    const __half* Ab = A + (size_t)row0 * lda;
    const __half* Bb = TRANSB ? (B + col0) : (B + (size_t)col0 * ldb);
    const uint32_t sbase = smem_u32(sm);

    const int ldr  = tid >> 3;
    const int ldcN = (tid & 7) * 8;

    auto load_stage = [&](int k0, int st) {
        const uint32_t abase = sbase + st * (STAGE_H * 2);
        const uint32_t bbase = abase + A_SZH * 2;
#pragma unroll
        for (int i = 0; i < 4; i++) {
            const int r = ldr + i * 32;
            cp16(abase + (r * RS + ldcN) * 2, Ab + (size_t)r * lda + k0 + ldcN);
        }
        if (TRANSB) {
#pragma unroll
            for (int i = 0; i < 4; i++) {
                const int id = tid + i * 256;
                const int r  = id >> 4;            // key row 0..63
                const int ch = (id & 15) * 8;      // halves within row
                cp16(bbase + r * RSB2 + ch * 2, Bb + (size_t)(k0 + r) * ldb + ch);
            }
        } else {
#pragma unroll
            for (int i = 0; i < 4; i++) {
                const int r = ldr + i * 32;
                cp16(bbase + (r * RS + ldcN) * 2, Bb + (size_t)r * ldb + k0 + ldcN);
            }
        }
        asm volatile("cp.async.commit_group;" ::: "memory");
    };

    const int quad = lane >> 3;
    const int r8   = lane & 7;
    uint32_t a_off[2], b_off[4];
#pragma unroll
    for (int mt = 0; mt < 2; mt++) {
        const int row = warp_m * 32 + mt * 16 + (lane & 15);
        a_off[mt] = (row * RS + (lane >> 4) * 8) * 2;
    }
    if (TRANSB) {
#pragma unroll
        for (int ntp = 0; ntp < 4; ntp++) {
            const int kk = (quad & 1) * 8 + r8;                        // key row
            const int nn = warp_n * 64 + ntp * 16 + (quad >> 1) * 8;   // d col
            b_off[ntp] = A_SZH * 2 + kk * RSB2 + nn * 2;
        }
    } else {
#pragma unroll
        for (int ntp = 0; ntp < 4; ntp++) {
            const int n = warp_n * 64 + ntp * 16 + (quad >> 1) * 8 + r8;
            b_off[ntp] = A_SZH * 2 + (n * RS + (quad & 1) * 8) * 2;
        }
    }
    const uint32_t koffB = TRANSB ? (16 * RSB2) : 32;

    float acc[2][8][4];
#pragma unroll
    for (int a = 0; a < 2; a++)
#pragma unroll
        for (int b = 0; b < 8; b++)
#pragma unroll
            for (int c = 0; c < 4; c++) acc[a][b][c] = 0.f;

    const int nk = K / BK;
    load_stage(0, 0);
    if (nk > 1) load_stage(BK, 1);

    int st = 0;
    for (int t = 0; t < nk; t++) {
        if (t + 1 < nk) asm volatile("cp.async.wait_group 1;" ::: "memory");
        else            asm volatile("cp.async.wait_group 0;" ::: "memory");
        __syncthreads();

        if (t + 2 < nk) {
            int st2 = st + 2; if (st2 >= NSTAGE) st2 -= NSTAGE;
            load_stage((t + 2) * BK, st2);
        }

        const uint32_t stbase = sbase + st * (STAGE_H * 2);

#pragma unroll
        for (int ks = 0; ks < 4; ks++) {
            const uint32_t koff = ks * 32;
            uint32_t a[2][4];
#pragma unroll
            for (int mt = 0; mt < 2; mt++)
                ldmx4(a[mt], stbase + a_off[mt] + koff);
            uint32_t b[8][2];
#pragma unroll
            for (int ntp = 0; ntp < 4; ntp++) {
                uint32_t tr[4];
                if (TRANSB) ldmx4t(tr, stbase + b_off[ntp] + ks * koffB);
                else        ldmx4 (tr, stbase + b_off[ntp] + ks * koffB);
                b[2*ntp][0]   = tr[0]; b[2*ntp][1]   = tr[1];
                b[2*ntp+1][0] = tr[2]; b[2*ntp+1][1] = tr[3];
            }
#pragma unroll
            for (int mt = 0; mt < 2; mt++)
#pragma unroll
                for (int nt = 0; nt < 8; nt++)
                    mma_f16(acc[mt][nt], a[mt][0], a[mt][1], a[mt][2], a[mt][3],
                            b[nt][0], b[nt][1]);
        }
        st++; if (st >= NSTAGE) st -= NSTAGE;
    }

    // Epilogue
    const int g  = lane >> 2;
    const int tg = lane & 3;
    if (out_half) {
        __half* C = (__half*)Cvoid + (size_t)batch * sC;
#pragma unroll
        for (int mt = 0; mt < 2; mt++)
#pragma unroll
            for (int hf = 0; hf < 2; hf++) {
                const int r = row0 + warp_m * 32 + mt * 16 + hf * 8 + g;
                __half* Crow = C + (size_t)r * ldc;
                const float rs = rowinv ? (1.f / rowinv[r]) : 1.f;
                float rowpart = 0.f;
#pragma unroll
                for (int nt = 0; nt < 8; nt++) {
                    const int cix = col0 + warp_n * 64 + nt * 8 + tg * 2;
                    float v0 = acc[mt][nt][hf * 2 + 0] * alpha;
                    float v1 = acc[mt][nt][hf * 2 + 1] * alpha;
                    if (bias) { v0 += bias[cix]; v1 += bias[cix + 1]; }
                    if (do_exp) {
                        v0 = __expf(v0 - ESHIFT); v1 = __expf(v1 - ESHIFT);
                        rowpart += v0 + v1;
                    }
                    v0 *= rs; v1 *= rs;
                    *(__half2*)&Crow[cix] = __floats2half2_rn(v0, v1);
                }
                if (do_exp) {
                    rowpart += __shfl_xor_sync(0xFFFFFFFF, rowpart, 1);
                    rowpart += __shfl_xor_sync(0xFFFFFFFF, rowpart, 2);
                    if (tg == 0 && rsum_out) atomicAdd(&rsum_out[r], rowpart);
                }
            }
    } else {
        float* C = (float*)Cvoid + (size_t)batch * sC;
        const float* R = resid ? resid + (size_t)batch * sC : nullptr;
#pragma unroll
        for (int mt = 0; mt < 2; mt++)
#pragma unroll
            for (int hf = 0; hf < 2; hf++) {
                const int r = row0 + warp_m * 32 + mt * 16 + hf * 8 + g;
                float* Crow = C + (size_t)r * ldc;
                const float* Rrow = R ? R + (size_t)r * ldc : nullptr;
#pragma unroll
                for (int nt = 0; nt < 8; nt++) {
                    const int cix = col0 + warp_n * 64 + nt * 8 + tg * 2;
                    float v0 = acc[mt][nt][hf * 2 + 0] * alpha;
                    float v1 = acc[mt][nt][hf * 2 + 1] * alpha;
                    if (bias) { v0 += bias[cix]; v1 += bias[cix + 1]; }
                    if (Rrow) { v0 += Rrow[cix]; v1 += Rrow[cix + 1]; }
                    *(float2*)&Crow[cix] = make_float2(v0, v1);
                }
            }
    }
}

// ---------------------------------------------------------------------------
// Launch
// ---------------------------------------------------------------------------
extern "C" void kernel_launch(void* const* d_in, const int* in_sizes, int n_in,
                              void* d_out, int out_size)
{
    const float* x   = (const float*)d_in[0];
    const float* gsc = (const float*)d_in[1];
    const float* gbi = (const float*)d_in[2];
    const float* Wq  = (const float*)d_in[3];
    const float* bq  = (const float*)d_in[4];
    const float* Wk  = (const float*)d_in[5];
    const float* bk  = (const float*)d_in[6];
    const float* Wv  = (const float*)d_in[7];
    const float* bv  = (const float*)d_in[8];
    const float* Wo  = (const float*)d_in[9];
    const float* bo  = (const float*)d_in[10];
    float* out = (float*)d_out;

    cudaFuncSetAttribute(mma_gemm<0>, cudaFuncAttributeMaxDynamicSharedMemorySize,
                         SMEM_BYTES);
    cudaFuncSetAttribute(mma_gemm<1>, cudaFuncAttributeMaxDynamicSharedMemorySize,
                         SMEM_BYTES);

    __half *ft, *qkv, *pb, *at, *wt;
    float *bqkv, *rsum;
    cudaGetSymbolAddress((void**)&ft,   g_ft);
    cudaGetSymbolAddress((void**)&qkv,  g_qkv);
    cudaGetSymbolAddress((void**)&pb,   g_p);
    cudaGetSymbolAddress((void**)&at,   g_at);
    cudaGetSymbolAddress((void**)&wt,   g_wt);
    cudaGetSymbolAddress((void**)&bqkv, g_bqkv);
    cudaGetSymbolAddress((void**)&rsum, g_rsum);

    const long long sQKV = (long long)SS * 3 * CC;
    const long long sBSS = (long long)SS * SS;
    const long long sBSC = (long long)SS * CC;

    // 1) GroupNorm (+rsum zero), weight transpose (+bias pack)
    gn_kernel<<<BB * GG, 256>>>(x, gsc, gbi);
    transpose_w<<<dim3(8, 8, 4), dim3(32, 8)>>>(Wq, Wk, Wv, Wo, bq, bk, bv);

    // 2) fused QKV projection -> half
    mma_gemm<0><<<dim3((3 * CC) / BN, MS / BM, 1), 256, SMEM_BYTES>>>(
        ft, wt, bqkv, nullptr, nullptr, nullptr, qkv,
        CC, CC, CC, 3 * CC, 1.f, 1, 0, 1, 0, 0, 0);

    // 3) u = exp(QK^T/16 - ESHIFT) per batch -> half; row sums accumulated
    mma_gemm<0><<<dim3(SS / BM, SS / BN, BB), 256, SMEM_BYTES>>>(
        qkv + 0, qkv + CC, nullptr, nullptr, nullptr, rsum, pb,
        CC, 3 * CC, 3 * CC, SS, 0.0625f, 1, 1, 0, sQKV, sQKV, sBSS);

    // 4) attn = (u V) / S per batch -> half; V read in [key][d] layout (TRANSB)
    mma_gemm<1><<<dim3(SS / BM, CC / BN, BB), 256, SMEM_BYTES>>>(
        pb, qkv + 2 * CC, nullptr, nullptr, rsum, nullptr, at,
        SS, SS, 3 * CC, CC, 1.f, 1, 0, 0, sBSS, sQKV, sBSC);

    // 5) out = attn Wo + bo + x -> f32
    mma_gemm<0><<<dim3(CC / BN, MS / BM, 1), 256, SMEM_BYTES>>>(
        at, wt + 3 * CC * CC, bo, x, nullptr, nullptr, out,
        CC, CC, CC, CC, 1.f, 0, 0, 1, 0, 0, 0);
}

// round 13
// speedup vs baseline: 1.2878x; 1.0761x over previous
#include <cuda_runtime.h>
#include <cuda_fp16.h>
#include <cstdint>
#include <cstddef>

// Problem constants
#define BB   32
#define HH   32
#define WW   32
#define CC   256
#define SS   (HH * WW)        // 1024
#define GG   32
#define CPG  (CC / GG)        // 8
#define MS   (BB * SS)        // 32768
#define EPS  1e-5f
#define ESHIFT 6.0f           // exp shift: u = exp(logit - ESHIFT)

// GEMM tile config (fp16 operands, fp32 accum) — R10/R12 proven geometry
#define BM 128
#define BN 128
#define BK 64
#define NSTAGE 3
#define RS 72                             // padded row stride in halves (144 B)
#define RSB2 272                          // TRANSB row stride in BYTES (136 halves)
#define A_SZH (BM * RS)
#define B_SZH (BN * RS)
#define STAGE_H (A_SZH + B_SZH)
#define SMEM_BYTES (NSTAGE * STAGE_H * 2) // 110592 bytes

// ---------------------------------------------------------------------------
// Scratch
// ---------------------------------------------------------------------------
__device__ __half g_ft  [(size_t)MS * CC];
__device__ __half g_qkv [(size_t)MS * 3 * CC];
__device__ __half g_p   [(size_t)BB * SS * SS];   // unnormalized exp(logits)
__device__ float  g_rsum[(size_t)MS];             // rowsum per (batch,query)
__device__ __half g_at  [(size_t)MS * CC];
__device__ __half g_wt  [4 * CC * CC];
__device__ float  g_bqkv[3 * CC];

// ---------------------------------------------------------------------------
// Helpers
// ---------------------------------------------------------------------------
__device__ __forceinline__ uint32_t smem_u32(const void* p) {
    uint32_t a;
    asm("{ .reg .u64 t; cvta.to.shared.u64 t, %1; cvt.u32.u64 %0, t; }" : "=r"(a) : "l"(p));
    return a;
}
__device__ __forceinline__ void cp16(uint32_t s, const void* g) {
    asm volatile("cp.async.cg.shared.global [%0], [%1], 16;" :: "r"(s), "l"(g));
}
__device__ __forceinline__ void ldmx4(uint32_t* r, uint32_t addr) {
    asm volatile("ldmatrix.sync.aligned.m8n8.x4.shared.b16 {%0,%1,%2,%3}, [%4];"
        : "=r"(r[0]), "=r"(r[1]), "=r"(r[2]), "=r"(r[3]) : "r"(addr));
}
__device__ __forceinline__ void ldmx4t(uint32_t* r, uint32_t addr) {
    asm volatile("ldmatrix.sync.aligned.m8n8.x4.trans.shared.b16 {%0,%1,%2,%3}, [%4];"
        : "=r"(r[0]), "=r"(r[1]), "=r"(r[2]), "=r"(r[3]) : "r"(addr));
}
__device__ __forceinline__ void mma_f16(float* d,
                                        uint32_t a0, uint32_t a1, uint32_t a2, uint32_t a3,
                                        uint32_t b0, uint32_t b1) {
    asm volatile(
        "mma.sync.aligned.m16n8k16.row.col.f32.f16.f16.f32 "
        "{%0,%1,%2,%3}, {%4,%5,%6,%7}, {%8,%9}, {%0,%1,%2,%3};"
        : "+f"(d[0]), "+f"(d[1]), "+f"(d[2]), "+f"(d[3])
        : "r"(a0), "r"(a1), "r"(a2), "r"(a3), "r"(b0), "r"(b1));
}

// ---------------------------------------------------------------------------
// GroupNorm -> fp16; blocks 0..31 also zero g_rsum (saves a launch)
// ---------------------------------------------------------------------------
__global__ void gn_kernel(const float* __restrict__ x,
                          const float* __restrict__ scale,
                          const float* __restrict__ bias)
{
    const int b = blockIdx.x / GG, g = blockIdx.x % GG, tid = threadIdx.x;

    if (blockIdx.x < 32) {
        float4* rz = (float4*)(g_rsum + (size_t)blockIdx.x * 1024);
        rz[tid] = make_float4(0.f, 0.f, 0.f, 0.f);
    }

    const float* xb = x + (size_t)b * SS * CC + g * CPG;

    float4 xv[4][2];
    float sum = 0.f, ssq = 0.f;
#pragma unroll
    for (int kk = 0; kk < 4; kk++) {
        const int s = tid + kk * 256;
        const float4* p = (const float4*)(xb + (size_t)s * CC);
        xv[kk][0] = p[0];
        xv[kk][1] = p[1];
        const float4 a = xv[kk][0], c = xv[kk][1];
        sum += a.x + a.y + a.z + a.w + c.x + c.y + c.z + c.w;
        ssq += a.x*a.x + a.y*a.y + a.z*a.z + a.w*a.w
             + c.x*c.x + c.y*c.y + c.z*c.z + c.w*c.w;
    }
    __shared__ float r0[256], r1[256];
    r0[tid] = sum; r1[tid] = ssq;
    __syncthreads();
    for (int off = 128; off > 0; off >>= 1) {
        if (tid < off) { r0[tid] += r0[tid + off]; r1[tid] += r1[tid + off]; }
        __syncthreads();
    }
    const float mean = r0[0] * (1.f / 8192.f);
    const float var  = r1[0] * (1.f / 8192.f) - mean * mean;
    const float inv  = rsqrtf(var + EPS);

    float sc[CPG], bi[CPG];
#pragma unroll
    for (int c = 0; c < CPG; c++) {
        sc[c] = scale[g * CPG + c] * inv;
        bi[c] = bias [g * CPG + c];
    }
    __half* fb = g_ft + (size_t)b * SS * CC + g * CPG;
#pragma unroll
    for (int kk = 0; kk < 4; kk++) {
        const int s = tid + kk * 256;
        __half2* fo = (__half2*)(fb + (size_t)s * CC);
        const float* xi = (const float*)&xv[kk][0];
#pragma unroll
        for (int c = 0; c < 4; c++) {
            const float v0 = (xi[2*c]   - mean) * sc[2*c]   + bi[2*c];
            const float v1 = (xi[2*c+1] - mean) * sc[2*c+1] + bi[2*c+1];
            fo[c] = __floats2half2_rn(v0, v1);
        }
    }
}

// ---------------------------------------------------------------------------
// Weight transpose -> fp16; block (0,0,0) also packs the QKV biases.
// ---------------------------------------------------------------------------
__global__ void transpose_w(const float* __restrict__ Wq, const float* __restrict__ Wk,
                            const float* __restrict__ Wv, const float* __restrict__ Wo,
                            const float* __restrict__ bq, const float* __restrict__ bk,
                            const float* __restrict__ bv)
{
    __shared__ float t[32][33];
    const int i = blockIdx.z;
    const float* W = (i == 0) ? Wq : (i == 1) ? Wk : (i == 2) ? Wv : Wo;
    const int kb = blockIdx.x * 32, nb = blockIdx.y * 32;
    const int tx = threadIdx.x, ty = threadIdx.y;
    const int tid = ty * 32 + tx;

    if (i == 0 && blockIdx.x == 0 && blockIdx.y == 0) {
        g_bqkv[tid]          = bq[tid];
        g_bqkv[tid + CC]     = bk[tid];
        g_bqkv[tid + 2 * CC] = bv[tid];
    }

#pragma unroll
    for (int j = 0; j < 4; j++)
        t[ty + j * 8][tx] = W[(size_t)(kb + ty + j * 8) * CC + nb + tx];
    __syncthreads();
    __half* out = g_wt + (size_t)i * CC * CC;
#pragma unroll
    for (int j = 0; j < 4; j++)
        out[(size_t)(nb + ty + j * 8) * CC + kb + tx] = __float2half_rn(t[tx][ty + j * 8]);
}

// ---------------------------------------------------------------------------
// fp16 tensor-core GEMM. CTA 128x128, warp 32x64, BK=64, 3-stage ring,
// ldmatrix.x4, 2 CTAs/SM.  K is a compile-time template parameter so the
// K-loop fully unrolls: ring indices and stage bases become literals.
// C[m,n] = alpha * sum_k A[m,k]*B[n,k] (+bias)(+resid)
// TRANSB: B stored [K,N] row-major (ldb = row stride); loaded via ldmatrix.trans.
// do_exp: out = exp(val - ESHIFT) (half) and accumulate row sums into rsum_out.
// rowinv: out *= 1/rowinv[batch*SS + r].
// ---------------------------------------------------------------------------
template <int TRANSB, int KDIM>
__global__ void __launch_bounds__(256, 2)
mma_gemm(const __half* __restrict__ A, const __half* __restrict__ B,
         const float* __restrict__ bias, const float* __restrict__ resid,
         const float* __restrict__ rowinv, float* __restrict__ rsum_out,
         void* __restrict__ Cvoid,
         int lda, int ldb, int ldc,
         float alpha, int out_half, int do_exp, int swapxy,
         long long sA, long long sB, long long sC)
{
    extern __shared__ __half sm[];
    const int batch = blockIdx.z;
    A += (size_t)batch * sA;
    B += (size_t)batch * sB;
    if (rowinv)   rowinv   += (size_t)batch * SS;
    if (rsum_out) rsum_out += (size_t)batch * SS;

    const int tid  = threadIdx.x;
    const int lane = tid & 31;
    const int wid  = tid >> 5;
    const int warp_m = wid & 3;
    const int warp_n = wid >> 2;
    const int bx = swapxy ? blockIdx.y : blockIdx.x;
    const int by = swapxy ? blockIdx.x : blockIdx.y;
    const int row0 = bx * BM;
    const int col0 = by * BN;

    const __half* Ab = A + (size_t)row0 * lda;
    const __half* Bb = TRANSB ? (B + col0) : (B + (size_t)col0 * ldb);
    const uint32_t sbase = smem_u32(sm);

    const int ldr  = tid >> 3;
    const int ldcN = (tid & 7) * 8;

    auto load_stage = [&](int k0, int st) {
        const uint32_t abase = sbase + st * (STAGE_H * 2);
        const uint32_t bbase = abase + A_SZH * 2;
#pragma unroll
        for (int i = 0; i < 4; i++) {
            const int r = ldr + i * 32;
            cp16(abase + (r * RS + ldcN) * 2, Ab + (size_t)r * lda + k0 + ldcN);
        }
        if (TRANSB) {
#pragma unroll
            for (int i = 0; i < 4; i++) {
                const int id = tid + i * 256;
                const int r  = id >> 4;            // key row 0..63
                const int ch = (id & 15) * 8;      // halves within row
                cp16(bbase + r * RSB2 + ch * 2, Bb + (size_t)(k0 + r) * ldb + ch);
            }
        } else {
#pragma unroll
            for (int i = 0; i < 4; i++) {
                const int r = ldr + i * 32;
                cp16(bbase + (r * RS + ldcN) * 2, Bb + (size_t)r * ldb + k0 + ldcN);
            }
        }
        asm volatile("cp.async.commit_group;" ::: "memory");
    };

    const int quad = lane >> 3;
    const int r8   = lane & 7;
    uint32_t a_off[2], b_off[4];
#pragma unroll
    for (int mt = 0; mt < 2; mt++) {
        const int row = warp_m * 32 + mt * 16 + (lane & 15);
        a_off[mt] = (row * RS + (lane >> 4) * 8) * 2;
    }
    if (TRANSB) {
#pragma unroll
        for (int ntp = 0; ntp < 4; ntp++) {
            const int kk = (quad & 1) * 8 + r8;                        // key row
            const int nn = warp_n * 64 + ntp * 16 + (quad >> 1) * 8;   // d col
            b_off[ntp] = A_SZH * 2 + kk * RSB2 + nn * 2;
        }
    } else {
#pragma unroll
        for (int ntp = 0; ntp < 4; ntp++) {
            const int n = warp_n * 64 + ntp * 16 + (quad >> 1) * 8 + r8;
            b_off[ntp] = A_SZH * 2 + (n * RS + (quad & 1) * 8) * 2;
        }
    }
    const uint32_t koffB = TRANSB ? (16 * RSB2) : 32;

    float acc[2][8][4];
#pragma unroll
    for (int a = 0; a < 2; a++)
#pragma unroll
        for (int b = 0; b < 8; b++)
#pragma unroll
            for (int c = 0; c < 4; c++) acc[a][b][c] = 0.f;

    constexpr int NK = KDIM / BK;
    load_stage(0, 0);
    if (NK > 1) load_stage(BK, 1);

#pragma unroll
    for (int t = 0; t < NK; t++) {
        constexpr int W1 = 1;
        if (t + 1 < NK) asm volatile("cp.async.wait_group %0;" :: "n"(W1) : "memory");
        else            asm volatile("cp.async.wait_group 0;" ::: "memory");
        __syncthreads();

        if (t + 2 < NK)
            load_stage((t + 2) * BK, (t + 2) % NSTAGE);

        const uint32_t stbase = sbase + (t % NSTAGE) * (STAGE_H * 2);

#pragma unroll
        for (int ks = 0; ks < 4; ks++) {
            const uint32_t koff = ks * 32;
            uint32_t a[2][4];
#pragma unroll
            for (int mt = 0; mt < 2; mt++)
                ldmx4(a[mt], stbase + a_off[mt] + koff);
            uint32_t b[8][2];
#pragma unroll
            for (int ntp = 0; ntp < 4; ntp++) {
                uint32_t tr[4];
                if (TRANSB) ldmx4t(tr, stbase + b_off[ntp] + ks * koffB);
                else        ldmx4 (tr, stbase + b_off[ntp] + ks * koffB);
                b[2*ntp][0]   = tr[0]; b[2*ntp][1]   = tr[1];
                b[2*ntp+1][0] = tr[2]; b[2*ntp+1][1] = tr[3];
            }
#pragma unroll
            for (int mt = 0; mt < 2; mt++)
#pragma unroll
                for (int nt = 0; nt < 8; nt++)
                    mma_f16(acc[mt][nt], a[mt][0], a[mt][1], a[mt][2], a[mt][3],
                            b[nt][0], b[nt][1]);
        }
    }

    // Epilogue
    const int g  = lane >> 2;
    const int tg = lane & 3;
    if (out_half) {
        __half* C = (__half*)Cvoid + (size_t)batch * sC;
#pragma unroll
        for (int mt = 0; mt < 2; mt++)
#pragma unroll
            for (int hf = 0; hf < 2; hf++) {
                const int r = row0 + warp_m * 32 + mt * 16 + hf * 8 + g;
                __half* Crow = C + (size_t)r * ldc;
                const float rs = rowinv ? (1.f / rowinv[r]) : 1.f;
                float rowpart = 0.f;
#pragma unroll
                for (int nt = 0; nt < 8; nt++) {
                    const int cix = col0 + warp_n * 64 + nt * 8 + tg * 2;
                    float v0 = acc[mt][nt][hf * 2 + 0] * alpha;
                    float v1 = acc[mt][nt][hf * 2 + 1] * alpha;
                    if (bias) { v0 += bias[cix]; v1 += bias[cix + 1]; }
                    if (do_exp) {
                        v0 = __expf(v0 - ESHIFT); v1 = __expf(v1 - ESHIFT);
                        rowpart += v0 + v1;
                    }
                    v0 *= rs; v1 *= rs;
                    *(__half2*)&Crow[cix] = __floats2half2_rn(v0, v1);
                }
                if (do_exp) {
                    rowpart += __shfl_xor_sync(0xFFFFFFFF, rowpart, 1);
                    rowpart += __shfl_xor_sync(0xFFFFFFFF, rowpart, 2);
                    if (tg == 0 && rsum_out) atomicAdd(&rsum_out[r], rowpart);
                }
            }
    } else {
        float* C = (float*)Cvoid + (size_t)batch * sC;
        const float* R = resid ? resid + (size_t)batch * sC : nullptr;
#pragma unroll
        for (int mt = 0; mt < 2; mt++)
#pragma unroll
            for (int hf = 0; hf < 2; hf++) {
                const int r = row0 + warp_m * 32 + mt * 16 + hf * 8 + g;
                float* Crow = C + (size_t)r * ldc;
                const float* Rrow = R ? R + (size_t)r * ldc : nullptr;
#pragma unroll
                for (int nt = 0; nt < 8; nt++) {
                    const int cix = col0 + warp_n * 64 + nt * 8 + tg * 2;
                    float v0 = acc[mt][nt][hf * 2 + 0] * alpha;
                    float v1 = acc[mt][nt][hf * 2 + 1] * alpha;
                    if (bias) { v0 += bias[cix]; v1 += bias[cix + 1]; }
                    if (Rrow) { v0 += Rrow[cix]; v1 += Rrow[cix + 1]; }
                    *(float2*)&Crow[cix] = make_float2(v0, v1);
                }
            }
    }
}

// ---------------------------------------------------------------------------
// Launch
// ---------------------------------------------------------------------------
extern "C" void kernel_launch(void* const* d_in, const int* in_sizes, int n_in,
                              void* d_out, int out_size)
{
    const float* x   = (const float*)d_in[0];
    const float* gsc = (const float*)d_in[1];
    const float* gbi = (const float*)d_in[2];
    const float* Wq  = (const float*)d_in[3];
    const float* bq  = (const float*)d_in[4];
    const float* Wk  = (const float*)d_in[5];
    const float* bk  = (const float*)d_in[6];
    const float* Wv  = (const float*)d_in[7];
    const float* bv  = (const float*)d_in[8];
    const float* Wo  = (const float*)d_in[9];
    const float* bo  = (const float*)d_in[10];
    float* out = (float*)d_out;

    cudaFuncSetAttribute((const void*)mma_gemm<0, 256>,
                         cudaFuncAttributeMaxDynamicSharedMemorySize, SMEM_BYTES);
    cudaFuncSetAttribute((const void*)mma_gemm<1, 1024>,
                         cudaFuncAttributeMaxDynamicSharedMemorySize, SMEM_BYTES);

    __half *ft, *qkv, *pb, *at, *wt;
    float *bqkv, *rsum;
    cudaGetSymbolAddress((void**)&ft,   g_ft);
    cudaGetSymbolAddress((void**)&qkv,  g_qkv);
    cudaGetSymbolAddress((void**)&pb,   g_p);
    cudaGetSymbolAddress((void**)&at,   g_at);
    cudaGetSymbolAddress((void**)&wt,   g_wt);
    cudaGetSymbolAddress((void**)&bqkv, g_bqkv);
    cudaGetSymbolAddress((void**)&rsum, g_rsum);

    const long long sQKV = (long long)SS * 3 * CC;
    const long long sBSS = (long long)SS * SS;
    const long long sBSC = (long long)SS * CC;

    // 1) GroupNorm (+rsum zero), weight transpose (+bias pack)
    gn_kernel<<<BB * GG, 256>>>(x, gsc, gbi);
    transpose_w<<<dim3(8, 8, 4), dim3(32, 8)>>>(Wq, Wk, Wv, Wo, bq, bk, bv);

    // 2) fused QKV projection -> half (K=256)
    mma_gemm<0, 256><<<dim3((3 * CC) / BN, MS / BM, 1), 256, SMEM_BYTES>>>(
        ft, wt, bqkv, nullptr, nullptr, nullptr, qkv,
        CC, CC, 3 * CC, 1.f, 1, 0, 1, 0, 0, 0);

    // 3) u = exp(QK^T/16 - ESHIFT) per batch -> half; row sums accumulated (K=256)
    mma_gemm<0, 256><<<dim3(SS / BM, SS / BN, BB), 256, SMEM_BYTES>>>(
        qkv + 0, qkv + CC, nullptr, nullptr, nullptr, rsum, pb,
        3 * CC, 3 * CC, SS, 0.0625f, 1, 1, 0, sQKV, sQKV, sBSS);

    // 4) attn = (u V) / S per batch -> half; V in [key][d] layout (TRANSB, K=1024)
    mma_gemm<1, 1024><<<dim3(SS / BM, CC / BN, BB), 256, SMEM_BYTES>>>(
        pb, qkv + 2 * CC, nullptr, nullptr, rsum, nullptr, at,
        SS, 3 * CC, CC, 1.f, 1, 0, 0, sBSS, sQKV, sBSC);

    // 5) out = attn Wo + bo + x -> f32 (K=256)
    mma_gemm<0, 256><<<dim3(CC / BN, MS / BM, 1), 256, SMEM_BYTES>>>(
        at, wt + 3 * CC * CC, bo, x, nullptr, nullptr, out,
        CC, CC, CC, 1.f, 0, 0, 1, 0, 0, 0);
}